// round 1
// baseline (speedup 1.0000x reference)
#include <cuda_runtime.h>
#include <stdint.h>

// Problem constants (KVCache_9526237462719):
//   input_pos: int32[S], k_val/v_val: f32[B,H,S,D], k_cache/v_cache: f32[B,H,BLOCK,D]
//   out = concat(k_out[:,:,:S,:], v_out[:,:,:S,:]) as f32
#define KB      4
#define KH      32
#define KS      1024
#define KD      128
#define KBLOCK  4096

#define D4      (KD / 4)                 // 32 float4 per row
#define HALF4   (KB * KH * KS * D4)      // float4 count per tensor = 4,194,304
#define TOTAL4  (2 * HALF4)              // 8,388,608

// Inverse scatter map: inv[p] = s such that input_pos[s] == p, else -1.
__device__ int g_inv[KS];

__global__ void inv_init_kernel() {
    int p = blockIdx.x * blockDim.x + threadIdx.x;
    if (p < KS) g_inv[p] = -1;
}

__global__ void inv_scatter_kernel(const int* __restrict__ input_pos) {
    int s = blockIdx.x * blockDim.x + threadIdx.x;
    if (s < KS) {
        int p = input_pos[s];
        if ((unsigned)p < (unsigned)KS) g_inv[p] = s;
    }
}

// Gather pass over the output. One float4 per thread, fully coalesced.
// Output layout: [k: (B,H,S,D)][v: (B,H,S,D)] flattened.
__global__ __launch_bounds__(256)
void kv_gather_kernel(const float4* __restrict__ k_val,
                      const float4* __restrict__ v_val,
                      const float4* __restrict__ k_cache,
                      const float4* __restrict__ v_cache,
                      float4* __restrict__ out) {
    unsigned i = blockIdx.x * 256u + threadIdx.x;   // < TOTAL4
    bool is_v = i >= (unsigned)HALF4;
    unsigned j = is_v ? i - (unsigned)HALF4 : i;

    unsigned d4  = j & (D4 - 1);        // low 5 bits
    unsigned row = j >> 5;              // (b*H + h)*S + p
    unsigned p   = row & (KS - 1);      // S = 1024
    unsigned bh  = row >> 10;

    const float4* __restrict__ val   = is_v ? v_val   : k_val;
    const float4* __restrict__ cache = is_v ? v_cache : k_cache;

    int s = g_inv[p];
    float4 r;
    if (s >= 0) {
        // val shape (B,H,S,D): row size D4, S rows per (b,h)
        r = val[(bh * KS + (unsigned)s) * D4 + d4];
    } else {
        // cache shape (B,H,BLOCK,D)
        r = cache[(bh * KBLOCK + p) * D4 + d4];
    }
    out[i] = r;
}

extern "C" void kernel_launch(void* const* d_in, const int* in_sizes, int n_in,
                              void* d_out, int out_size) {
    const int*    input_pos = (const int*)d_in[0];
    const float4* k_val     = (const float4*)d_in[1];
    const float4* v_val     = (const float4*)d_in[2];
    const float4* k_cache   = (const float4*)d_in[3];
    const float4* v_cache   = (const float4*)d_in[4];
    float4*       out       = (float4*)d_out;

    inv_init_kernel<<<(KS + 255) / 256, 256>>>();
    inv_scatter_kernel<<<(KS + 255) / 256, 256>>>(input_pos);
    kv_gather_kernel<<<TOTAL4 / 256, 256>>>(k_val, v_val, k_cache, v_cache, out);
}

// round 2
// speedup vs baseline: 1.0470x; 1.0470x over previous
#include <cuda_runtime.h>
#include <stdint.h>

// KVCache_9526237462719:
//   input_pos: int32[S], k_val/v_val: f32[B,H,S,D], k_cache/v_cache: f32[B,H,BLOCK,D]
//   out = [k_cache.at[:,:,pos].set(k_val)[:,:,:S,:], same for v] concatenated, f32.
#define KB      4
#define KH      32
#define KS      1024
#define KD      128
#define KBLOCK  4096

#define D4      (KD / 4)                 // 32 float4 per row
#define HALF4   (KB * KH * KS * D4)      // 4,194,304 float4 per tensor
#define TOTAL4  (2u * HALF4)             // 8,388,608

#define NTHREADS 512
#define NBLOCKS  1184                    // 148 SMs * 8

// Single fused kernel: build the inverse scatter map (pos -> source index s)
// in shared memory per block, then grid-stride gather over the whole output.
__global__ __launch_bounds__(NTHREADS)
void kv_fused_kernel(const int*    __restrict__ input_pos,
                     const float4* __restrict__ k_val,
                     const float4* __restrict__ v_val,
                     const float4* __restrict__ k_cache,
                     const float4* __restrict__ v_cache,
                     float4*       __restrict__ out) {
    __shared__ int inv[KS];

    // Build inv[p] = s with input_pos[s] == p, else -1.  KS == 2*NTHREADS.
    #pragma unroll
    for (int t = threadIdx.x; t < KS; t += NTHREADS) inv[t] = -1;
    __syncthreads();
    #pragma unroll
    for (int s = threadIdx.x; s < KS; s += NTHREADS) {
        int p = input_pos[s];
        if ((unsigned)p < (unsigned)KS) inv[p] = s;
    }
    __syncthreads();

    // Grid-stride gather: one float4 per iteration, fully coalesced.
    const unsigned stride = NTHREADS * NBLOCKS;
    for (unsigned i = blockIdx.x * NTHREADS + threadIdx.x; i < TOTAL4; i += stride) {
        bool     is_v = i >= (unsigned)HALF4;
        unsigned j    = is_v ? i - (unsigned)HALF4 : i;

        unsigned d4  = j & (D4 - 1);     // low 5 bits
        unsigned row = j >> 5;           // (b*H + h)*S + p
        unsigned p   = row & (KS - 1);   // S = 1024
        unsigned bh  = row >> 10;

        const float4* __restrict__ val   = is_v ? v_val   : k_val;
        const float4* __restrict__ cache = is_v ? v_cache : k_cache;

        int s = inv[p];
        float4 r;
        if (s >= 0) {
            r = val[(bh * KS + (unsigned)s) * D4 + d4];      // (B,H,S,D)
        } else {
            r = cache[(bh * KBLOCK + p) * D4 + d4];          // (B,H,BLOCK,D)
        }
        out[i] = r;
    }
}

extern "C" void kernel_launch(void* const* d_in, const int* in_sizes, int n_in,
                              void* d_out, int out_size) {
    const int*    input_pos = (const int*)d_in[0];
    const float4* k_val     = (const float4*)d_in[1];
    const float4* v_val     = (const float4*)d_in[2];
    const float4* k_cache   = (const float4*)d_in[3];
    const float4* v_cache   = (const float4*)d_in[4];
    float4*       out       = (float4*)d_out;

    kv_fused_kernel<<<NBLOCKS, NTHREADS>>>(input_pos, k_val, v_val,
                                           k_cache, v_cache, out);
}

// round 3
// speedup vs baseline: 1.0901x; 1.0411x over previous
#include <cuda_runtime.h>
#include <stdint.h>

// KVCache_9526237462719:
//   input_pos: int32[S], k_val/v_val: f32[B,H,S,D], k_cache/v_cache: f32[B,H,BLOCK,D]
//   out = [k_cache.at[:,:,pos].set(k_val)[:,:,:S,:], same for v] concat, f32.
#define KB      4
#define KH      32
#define KS      1024
#define KD      128
#define KBLOCK  4096

#define D4      (KD / 4)                 // 32 float4 per row
#define HALF4   (KB * KH * KS * D4)      // 4,194,304 float4 per tensor
#define TOTAL4  (2u * HALF4)             // 8,388,608

#define NTHREADS 512
#define UNROLL   4
#define NBLOCKS  (TOTAL4 / (NTHREADS * UNROLL))   // 4096, exact — no tail

__device__ __forceinline__ const float4* src_addr(
    unsigned i, const int* __restrict__ inv,
    const float4* __restrict__ k_val,   const float4* __restrict__ v_val,
    const float4* __restrict__ k_cache, const float4* __restrict__ v_cache) {
    bool     is_v = i >= (unsigned)HALF4;
    unsigned j    = is_v ? i - (unsigned)HALF4 : i;
    unsigned d4   = j & (D4 - 1);
    unsigned row  = j >> 5;              // (b*H+h)*S + p
    unsigned p    = row & (KS - 1);
    unsigned bh   = row >> 10;
    int s = inv[p];
    if (s >= 0) {
        const float4* val = is_v ? v_val : k_val;
        return val + ((bh * KS + (unsigned)s) * D4 + d4);       // (B,H,S,D)
    } else {
        const float4* cache = is_v ? v_cache : k_cache;
        return cache + ((bh * KBLOCK + p) * D4 + d4);           // (B,H,BLOCK,D)
    }
}

__global__ __launch_bounds__(NTHREADS)
void kv_fused_kernel(const int*    __restrict__ input_pos,
                     const float4* __restrict__ k_val,
                     const float4* __restrict__ v_val,
                     const float4* __restrict__ k_cache,
                     const float4* __restrict__ v_cache,
                     float4*       __restrict__ out) {
    __shared__ int inv[KS];

    // Build inv[p] = s with input_pos[s] == p, else -1.  KS == 2*NTHREADS.
    #pragma unroll
    for (int t = threadIdx.x; t < KS; t += NTHREADS) inv[t] = -1;
    __syncthreads();
    #pragma unroll
    for (int s = threadIdx.x; s < KS; s += NTHREADS) {
        int p = input_pos[s];
        if ((unsigned)p < (unsigned)KS) inv[p] = s;
    }
    __syncthreads();

    // UNROLL independent chunks per thread at grid-stride offsets.
    // All accesses 16B, fully coalesced; loads batched for MLP, then stores.
    const unsigned stride = NTHREADS * NBLOCKS;
    unsigned i0 = blockIdx.x * NTHREADS + threadIdx.x;

    float4 r[UNROLL];
    #pragma unroll
    for (int u = 0; u < UNROLL; u++) {
        r[u] = __ldcs(src_addr(i0 + u * stride, inv,
                               k_val, v_val, k_cache, v_cache));
    }
    #pragma unroll
    for (int u = 0; u < UNROLL; u++) {
        __stcs(out + (i0 + u * stride), r[u]);
    }
}

extern "C" void kernel_launch(void* const* d_in, const int* in_sizes, int n_in,
                              void* d_out, int out_size) {
    const int*    input_pos = (const int*)d_in[0];
    const float4* k_val     = (const float4*)d_in[1];
    const float4* v_val     = (const float4*)d_in[2];
    const float4* k_cache   = (const float4*)d_in[3];
    const float4* v_cache   = (const float4*)d_in[4];
    float4*       out       = (float4*)d_out;

    kv_fused_kernel<<<NBLOCKS, NTHREADS>>>(input_pos, k_val, v_val,
                                           k_cache, v_cache, out);
}